// round 17
// baseline (speedup 1.0000x reference)
#include <cuda_runtime.h>
#include <cuda_bf16.h>

#define N_NODES 100000
#define N_EDGES 1600000
#define D 64
#define NEG_SLOPE 0.1f
#define CAP 64                // padded CSR stride; P(deg>64) ~ 1e-18 (Poisson 16)
#define LOG2E 1.4426950408889634f

// Scratch (__device__ globals; no allocation allowed).
// Zero-initialized at module load; every value ever stored in g_psrc is a
// valid node id (initial 0 or a written src id) -> reads need no clamping.
__device__ int g_cnt[N_NODES];          // per-node in-degree (and build cursor)
__device__ int g_psrc[N_NODES * CAP];   // padded CSR: src ids of node v at [v*64, v*64+deg)

// ---------------------------------------------------------------------------
// K1: single-pass padded-CSR build. 4 edges per thread (int4).
// ---------------------------------------------------------------------------
__global__ void k_build(const int4* __restrict__ src4,
                        const int4* __restrict__ dst4) {
    int i = blockIdx.x * blockDim.x + threadIdx.x;
    if (i < N_EDGES / 4) {
        int4 s = __ldg(&src4[i]);
        int4 d = __ldg(&dst4[i]);
        int p0 = atomicAdd(&g_cnt[d.x], 1);
        int p1 = atomicAdd(&g_cnt[d.y], 1);
        int p2 = atomicAdd(&g_cnt[d.z], 1);
        int p3 = atomicAdd(&g_cnt[d.w], 1);
        if (p0 < CAP) __stcg(&g_psrc[(d.x << 6) + p0], s.x);
        if (p1 < CAP) __stcg(&g_psrc[(d.y << 6) + p1], s.y);
        if (p2 < CAP) __stcg(&g_psrc[(d.z << 6) + p2], s.z);
        if (p3 < CAP) __stcg(&g_psrc[(d.w << 6) + p3], s.w);
    }
}

__device__ __forceinline__ float ex2f(float x) {
    float r;
    asm("ex2.approx.ftz.f32 %0, %1;" : "=f"(r) : "f"(x));
    return r;
}

// ---------------------------------------------------------------------------
// K2: fused GAT node kernel (R14 structure — best measured). One warp per
//     dst node, 2 edges/iteration (16 lanes x float4 per edge), loop split
//     at k=14 to hoist the sid0/sid1 stage select, odd tail at half weight.
//     NEW: LeakyReLU folded into the dot via |x|:
//        leaky(x) = 0.55x + 0.45|x|   (slope 0.1)
//        p = sum a55_i*x_i + a45_i*|x_i|,  a55/a45 prescaled by log2(e)
//     -> 12 instr for leaky+dot per iteration (FADD + 2xFFMA per feature,
//        |x| is an operand modifier), two partial accumulators for ILP.
// ---------------------------------------------------------------------------
__global__ void __launch_bounds__(128, 12) k_node(const float* __restrict__ h,
                                                  const float* __restrict__ aw,
                                                  float* __restrict__ out) {
    int gw   = (blockIdx.x * blockDim.x + threadIdx.x) >> 5;
    int lane = threadIdx.x & 31;
    if (gw >= N_NODES) return;
    int half = lane >> 4;      // edge slot within pair: 0 or 1
    int sub  = lane & 15;      // feature slice: floats [sub*4, sub*4+4)

    int beg = gw << 6;                      // padded CSR base
    int deg = __ldg(&g_cnt[gw]);
    if (deg > CAP) deg = CAP;
    int npair = deg >> 1;                   // full-pair iterations (<= 32)

    // preload all 64 padded slots (streaming: no reuse)
    int sid0 = __ldcg(&g_psrc[beg + lane]);        // slots  0..31
    int sid1 = __ldcg(&g_psrc[beg + 32 + lane]);   // slots 32..63

    float4 hv  = __ldg(&((const float4*)(h + (size_t)gw * D))[sub]);
    float4 awv = __ldg(&((const float4*)aw)[sub]);
    float4 a55, a45;
    a55.x = 0.55f * LOG2E * awv.x;  a45.x = 0.45f * LOG2E * awv.x;
    a55.y = 0.55f * LOG2E * awv.y;  a45.y = 0.45f * LOG2E * awv.y;
    a55.z = 0.55f * LOG2E * awv.z;  a45.z = 0.45f * LOG2E * awv.z;
    a55.w = 0.55f * LOG2E * awv.w;  a45.w = 0.45f * LOG2E * awv.w;

    float4 acc = make_float4(0.f, 0.f, 0.f, 0.f);
    float  den = 0.f;

    // depth-2 prefetch: iteration k uses slot 2k+half
    float4 r0, r1;
    {
        int s = __shfl_sync(0xffffffffu, sid0, half);
        r0 = __ldg(&((const float4*)(h + (size_t)s * D))[sub]);
        int s1 = __shfl_sync(0xffffffffu, sid0, 2 + half);
        r1 = __ldg(&((const float4*)(h + (size_t)s1 * D))[sub]);
    }

#define EDGE_BODY(CUR)                                                        \
    {                                                                         \
        float x0 = hv.x + (CUR).x;                                            \
        float x1 = hv.y + (CUR).y;                                            \
        float x2 = hv.z + (CUR).z;                                            \
        float x3 = hv.w + (CUR).w;                                            \
        float pa = a55.x * x0;                                                \
        float pb = a55.y * x1;                                                \
        pa = fmaf(a45.x, fabsf(x0), pa);                                      \
        pb = fmaf(a45.y, fabsf(x1), pb);                                      \
        pa = fmaf(a55.z, x2, pa);                                             \
        pb = fmaf(a55.w, x3, pb);                                             \
        pa = fmaf(a45.z, fabsf(x2), pa);                                      \
        pb = fmaf(a45.w, fabsf(x3), pb);                                      \
        float p = pa + pb;                                                    \
        p += __shfl_xor_sync(0xffffffffu, p, 8);                              \
        p += __shfl_xor_sync(0xffffffffu, p, 4);                              \
        p += __shfl_xor_sync(0xffffffffu, p, 2);                              \
        p += __shfl_xor_sync(0xffffffffu, p, 1);                              \
        float wgt = ex2f(p);                                                  \
        den   += wgt;                                                         \
        acc.x += wgt * (CUR).x;                                               \
        acc.y += wgt * (CUR).y;                                               \
        acc.z += wgt * (CUR).z;                                               \
        acc.w += wgt * (CUR).w;                                               \
    }

    // loop A: k in [0, min(npair,14)) — prefetch slots 2(k+2)+half < 32 -> sid0
    int kA = npair < 14 ? npair : 14;
    int k = 0;
    for (; k < kA; k++) {
        float4 cur = r0;
        r0 = r1;
        int s = __shfl_sync(0xffffffffu, sid0, 2 * k + 4 + half);
        r1 = __ldg(&((const float4*)(h + (size_t)s * D))[sub]);
        EDGE_BODY(cur)
    }
    // loop B: k in [14, npair) — prefetch slots >= 32 -> sid1
    for (; k < npair; k++) {
        float4 cur = r0;
        r0 = r1;
        int s = __shfl_sync(0xffffffffu, sid1, 2 * k + 4 - 32 + half);
        r1 = __ldg(&((const float4*)(h + (size_t)s * D))[sub]);
        EDGE_BODY(cur)
    }

    // odd tail: both halves process the last edge with half weight
    if (deg & 1) {                            // warp-uniform branch
        int pos = deg - 1;
        int staged = (pos < 32) ? sid0 : sid1;
        int s = __shfl_sync(0xffffffffu, staged, pos & 31);
        float4 cur = __ldg(&((const float4*)(h + (size_t)s * D))[sub]);
        float x0 = hv.x + cur.x;
        float x1 = hv.y + cur.y;
        float x2 = hv.z + cur.z;
        float x3 = hv.w + cur.w;
        float pa = a55.x * x0;
        float pb = a55.y * x1;
        pa = fmaf(a45.x, fabsf(x0), pa);
        pb = fmaf(a45.y, fabsf(x1), pb);
        pa = fmaf(a55.z, x2, pa);
        pb = fmaf(a55.w, x3, pb);
        pa = fmaf(a45.z, fabsf(x2), pa);
        pb = fmaf(a45.w, fabsf(x3), pb);
        float p = pa + pb;
        p += __shfl_xor_sync(0xffffffffu, p, 8);
        p += __shfl_xor_sync(0xffffffffu, p, 4);
        p += __shfl_xor_sync(0xffffffffu, p, 2);
        p += __shfl_xor_sync(0xffffffffu, p, 1);
        float wgt = 0.5f * ex2f(p);           // halves sum to 2^p exactly
        den   += wgt;
        acc.x += wgt * cur.x;
        acc.y += wgt * cur.y;
        acc.z += wgt * cur.z;
        acc.w += wgt * cur.w;
    }

    // merge the two halves (lanes l and l^16 share a feature slice)
    den   += __shfl_xor_sync(0xffffffffu, den,   16);
    acc.x += __shfl_xor_sync(0xffffffffu, acc.x, 16);
    acc.y += __shfl_xor_sync(0xffffffffu, acc.y, 16);
    acc.z += __shfl_xor_sync(0xffffffffu, acc.z, 16);
    acc.w += __shfl_xor_sync(0xffffffffu, acc.w, 16);

    float inv = (den > 0.f) ? (1.f / den) : 0.f;      // deg-0 nodes -> zeros
    if (half == 0)
        ((float4*)(out + (size_t)gw * D))[sub] =
            make_float4(acc.x * inv, acc.y * inv, acc.z * inv, acc.w * inv);
#undef EDGE_BODY
}

extern "C" void kernel_launch(void* const* d_in, const int* in_sizes, int n_in,
                              void* d_out, int out_size) {
    const float* h   = (const float*)d_in[0];
    const float* aw  = (const float*)d_in[1];
    const int*   src = (const int*)d_in[2];
    const int*   dst = (const int*)d_in[3];
    float* out = (float*)d_out;

    // zero the degree counters via a memset node (replaces a kernel launch)
    void* cnt_ptr = nullptr;
    cudaGetSymbolAddress(&cnt_ptr, g_cnt);
    cudaMemsetAsync(cnt_ptr, 0, N_NODES * sizeof(int));

    k_build<<<(N_EDGES / 4 + 255) / 256, 256>>>((const int4*)src, (const int4*)dst);

    long long t = (long long)N_NODES * 32;
    k_node<<<(int)((t + 127) / 128), 128>>>(h, aw, out);
}